// round 14
// baseline (speedup 1.0000x reference)
#include <cuda_runtime.h>
#include <math.h>

#define DINL __device__ __forceinline__

constexpr int NN  = 100000;
constexpr int EE  = 1600000;
constexpr int EP  = EE + NN;
constexpr int HH  = 4;
constexpr int CC  = 32;
constexpr int HC  = 128;
constexpr int EDD = 16;
constexpr float SLOPE = 0.2f;
constexpr int SCAN_B = 1024;
constexpr int SCAN_G = (NN + SCAN_B - 1) / SCAN_B;   // 98

// ---------------- scratch ----------------
__device__ float g_h1[NN * HC];
__device__ float g_x1[NN * HC];
__device__ float g_g2[NN * CC];
__device__ float g_alS1[NN * HH], g_alD1[NN * HH];
__device__ float g_alS2[NN],      g_alD2[NN];
__device__ float g_alE1c[EE * HH];   // eattr logit fold, CSR slot order, layer 1
__device__ float g_alE2c[EE];        // CSR slot order, layer 2
__device__ float g_p2c[EE];          // exp(logit), CSR order, layer 2
__device__ float g_v1e[EDD * HH];
__device__ float g_v2e[EDD];
__device__ float g_aes1[NN * HH];
__device__ float g_aes2[NN];
__device__ float g_es1[NN * HH];
__device__ float g_es2[NN];
// CSR over real edges only (no self loops)
__device__ int   g_count[NN];        // in-degree (kept intact by scan)
__device__ int   g_rowptr[NN + 1];
__device__ int   g_cursor[NN];
__device__ int   g_cs[EE];           // src node per CSR slot
__device__ int   g_cd[EE];           // dst node per CSR slot
__device__ int   g_ce[EE];           // original edge id per CSR slot (alpha output only)
__device__ int   g_epos[EE];         // edge id -> CSR slot
__device__ int   g_bsum[128];

DINL float lrelu1(float x) { return x >= 0.f ? x : SLOPE * x; }
DINL float elu1(float x)   { return x > 0.f ? x : expm1f(x); }

// packed fp32x2 (exonerated: R3/R6 showed identical results to scalar)
DINL unsigned long long pack2(float x, float y) {
    unsigned long long r;
    asm("mov.b64 %0, {%1, %2};" : "=l"(r) : "f"(x), "f"(y));
    return r;
}
DINL unsigned long long ffma2(unsigned long long a, unsigned long long b, unsigned long long c) {
    unsigned long long d;
    asm("fma.rn.f32x2 %0, %1, %2, %3;" : "=l"(d) : "l"(a), "l"(b), "l"(c));
    return d;
}
DINL float2 unpack2(unsigned long long v) {
    float2 r;
    asm("mov.b64 {%0, %1}, %2;" : "=f"(r.x), "=f"(r.y) : "l"(v));
    return r;
}

// ---------------- zero scratch ----------------
__global__ void k_zero() {
    int t = blockIdx.x * blockDim.x + threadIdx.x;
    int stride = gridDim.x * blockDim.x;
    for (int i = t; i < NN * HH; i += stride) g_aes1[i] = 0.f;
    for (int i = t; i < NN;      i += stride) { g_aes2[i] = 0.f; g_count[i] = 0; }
}

// ---------------- fold: v = We . a_e ----------------
__global__ void k_prep(const float* __restrict__ W1e, const float* __restrict__ a1e,
                       const float* __restrict__ W2e, const float* __restrict__ a2e) {
    int t = threadIdx.x;
    if (t < EDD * HH) {
        int d = t >> 2, h = t & 3;
        float s = 0.f;
        for (int c = 0; c < CC; c++) s += W1e[d * HC + h * CC + c] * a1e[h * CC + c];
        g_v1e[d * HH + h] = s;
    }
    if (t < EDD) {
        float s = 0.f;
        for (int c = 0; c < CC; c++) s += W2e[t * CC + c] * a2e[c];
        g_v2e[t] = s;
    }
}

// ---------------- CSR build (real edges only) ----------------
__global__ void k_csr_count(const int* __restrict__ ei) {
    int e = blockIdx.x * blockDim.x + threadIdx.x;
    if (e < EE) atomicAdd(&g_count[ei[EE + e]], 1);
}
__global__ void k_scan_part() {
    __shared__ int sm[SCAN_B];
    int idx = blockIdx.x * SCAN_B + threadIdx.x;
    sm[threadIdx.x] = (idx < NN) ? g_count[idx] : 0;
    __syncthreads();
    for (int o = SCAN_B / 2; o; o >>= 1) {
        if (threadIdx.x < o) sm[threadIdx.x] += sm[threadIdx.x + o];
        __syncthreads();
    }
    if (threadIdx.x == 0) g_bsum[blockIdx.x] = sm[0];
}
__global__ void k_scan_top() {
    __shared__ int sm[128];
    int t = threadIdx.x;
    int v = (t < SCAN_G) ? g_bsum[t] : 0;
    sm[t] = v;
    __syncthreads();
    for (int o = 1; o < 128; o <<= 1) {
        int add = (t >= o) ? sm[t - o] : 0;
        __syncthreads();
        sm[t] += add;
        __syncthreads();
    }
    g_bsum[t] = sm[t] - v;   // exclusive block offsets
}
__global__ void k_scan_down() {
    __shared__ int sm[SCAN_B];
    int t = threadIdx.x;
    int idx = blockIdx.x * SCAN_B + t;
    int v = (idx < NN) ? g_count[idx] : 0;
    sm[t] = v;
    __syncthreads();
    for (int o = 1; o < SCAN_B; o <<= 1) {
        int add = (t >= o) ? sm[t - o] : 0;
        __syncthreads();
        sm[t] += add;
        __syncthreads();
    }
    if (idx < NN) g_rowptr[idx] = g_bsum[blockIdx.x] + sm[t] - v;  // exclusive
    if (idx == 0) g_rowptr[NN] = EE;
}
__global__ void k_cursor() {
    int n = blockIdx.x * blockDim.x + threadIdx.x;
    if (n < NN) g_cursor[n] = g_rowptr[n];
}
__global__ void k_csr_scatter(const int* __restrict__ ei) {
    int e = blockIdx.x * blockDim.x + threadIdx.x;
    if (e < EE) {
        int s = ei[e];
        int d = ei[EE + e];
        int pos = atomicAdd(&g_cursor[d], 1);
        g_cs[pos] = s;
        g_cd[pos] = d;
        g_ce[pos] = e;
        g_epos[e] = pos;
    }
}

// ---------------- per-edge logit contributions (CSR-ordered) + dst-sums ----------------
__global__ void k_edge_al(const float* __restrict__ eattr, const int* __restrict__ ei) {
    int e = blockIdx.x * blockDim.x + threadIdx.x;
    if (e >= EE) return;
    const float4* ea4 = (const float4*)(eattr + e * EDD);
    float a0 = 0.f, a1 = 0.f, a2 = 0.f, a3 = 0.f, s2 = 0.f;
    #pragma unroll
    for (int q = 0; q < 4; q++) {
        float4 v = ea4[q];
        int d0 = q * 4;
        a0 += v.x * g_v1e[d0 * 4 + 0] + v.y * g_v1e[(d0+1) * 4 + 0]
            + v.z * g_v1e[(d0+2) * 4 + 0] + v.w * g_v1e[(d0+3) * 4 + 0];
        a1 += v.x * g_v1e[d0 * 4 + 1] + v.y * g_v1e[(d0+1) * 4 + 1]
            + v.z * g_v1e[(d0+2) * 4 + 1] + v.w * g_v1e[(d0+3) * 4 + 1];
        a2 += v.x * g_v1e[d0 * 4 + 2] + v.y * g_v1e[(d0+1) * 4 + 2]
            + v.z * g_v1e[(d0+2) * 4 + 2] + v.w * g_v1e[(d0+3) * 4 + 2];
        a3 += v.x * g_v1e[d0 * 4 + 3] + v.y * g_v1e[(d0+1) * 4 + 3]
            + v.z * g_v1e[(d0+2) * 4 + 3] + v.w * g_v1e[(d0+3) * 4 + 3];
        s2 += v.x * g_v2e[d0] + v.y * g_v2e[d0+1] + v.z * g_v2e[d0+2] + v.w * g_v2e[d0+3];
    }
    int pos = g_epos[e];
    *(float4*)&g_alE1c[pos * 4] = make_float4(a0, a1, a2, a3);
    g_alE2c[pos] = s2;
    int d = ei[EE + e];
    atomicAdd(&g_aes1[d * 4 + 0], a0);
    atomicAdd(&g_aes1[d * 4 + 1], a1);
    atomicAdd(&g_aes1[d * 4 + 2], a2);
    atomicAdd(&g_aes1[d * 4 + 3], a3);
    atomicAdd(&g_aes2[d], s2);
}

// ---------------- f32x2 register-blocked GEMMs (4 rows x 4 cols / thread) ----------------
__global__ void k_mm1(const float* __restrict__ x, const float* __restrict__ W1) {
    int t = blockIdx.x * blockDim.x + threadIdx.x;
    if (t >= (NN / 4) * 32) return;
    int nb = t >> 5;
    int j4 = (t & 31) * 4;
    int n0 = nb * 4;
    unsigned long long accL[4], accH[4];
    #pragma unroll
    for (int i = 0; i < 4; i++) { accL[i] = 0ULL; accH[i] = 0ULL; }
    for (int k = 0; k < 128; k += 4) {
        float4 xv[4];
        #pragma unroll
        for (int i = 0; i < 4; i++)
            xv[i] = *(const float4*)&x[(n0 + i) * 128 + k];
        #pragma unroll
        for (int kk = 0; kk < 4; kk++) {
            float4 w = *(const float4*)&W1[(k + kk) * 128 + j4];
            unsigned long long wL = pack2(w.x, w.y);
            unsigned long long wH = pack2(w.z, w.w);
            #pragma unroll
            for (int i = 0; i < 4; i++) {
                float xs = (kk == 0) ? xv[i].x : (kk == 1) ? xv[i].y : (kk == 2) ? xv[i].z : xv[i].w;
                unsigned long long xp = pack2(xs, xs);
                accL[i] = ffma2(xp, wL, accL[i]);
                accH[i] = ffma2(xp, wH, accH[i]);
            }
        }
    }
    #pragma unroll
    for (int i = 0; i < 4; i++) {
        float2 lo = unpack2(accL[i]);
        float2 hi = unpack2(accH[i]);
        *(float4*)&g_h1[(n0 + i) * 128 + j4] = make_float4(lo.x, lo.y, hi.x, hi.y);
    }
}
__global__ void k_mm2(const float* __restrict__ W2) {
    int t = blockIdx.x * blockDim.x + threadIdx.x;
    if (t >= (NN / 4) * 8) return;
    int nb = t >> 3;
    int j4 = (t & 7) * 4;
    int n0 = nb * 4;
    unsigned long long accL[4], accH[4];
    #pragma unroll
    for (int i = 0; i < 4; i++) { accL[i] = 0ULL; accH[i] = 0ULL; }
    for (int k = 0; k < 128; k += 4) {
        float4 xv[4];
        #pragma unroll
        for (int i = 0; i < 4; i++)
            xv[i] = *(const float4*)&g_x1[(n0 + i) * 128 + k];
        #pragma unroll
        for (int kk = 0; kk < 4; kk++) {
            float4 w = *(const float4*)&W2[(k + kk) * 32 + j4];
            unsigned long long wL = pack2(w.x, w.y);
            unsigned long long wH = pack2(w.z, w.w);
            #pragma unroll
            for (int i = 0; i < 4; i++) {
                float xs = (kk == 0) ? xv[i].x : (kk == 1) ? xv[i].y : (kk == 2) ? xv[i].z : xv[i].w;
                unsigned long long xp = pack2(xs, xs);
                accL[i] = ffma2(xp, wL, accL[i]);
                accH[i] = ffma2(xp, wH, accH[i]);
            }
        }
    }
    #pragma unroll
    for (int i = 0; i < 4; i++) {
        float2 lo = unpack2(accL[i]);
        float2 hi = unpack2(accH[i]);
        *(float4*)&g_g2[(n0 + i) * 32 + j4] = make_float4(lo.x, lo.y, hi.x, hi.y);
    }
}

// ---------------- per-node attention scalars + self logit (fused) ----------------
__global__ void k_nodal1(const float* __restrict__ a1s, const float* __restrict__ a1d) {
    int t = blockIdx.x * blockDim.x + threadIdx.x;
    if (t >= NN * HH) return;
    int n = t >> 2, h = t & 3;
    float s = 0.f, d = 0.f;
    for (int c = 0; c < CC; c++) {
        float hv = g_h1[n * HC + h * CC + c];
        s += hv * a1s[h * CC + c];
        d += hv * a1d[h * CC + c];
    }
    g_alS1[t] = s;
    g_alD1[t] = d;
    int dg = g_count[n];
    float inv = 1.f / (float)(dg > 0 ? dg : 1);
    g_es1[t] = lrelu1(s + d + g_aes1[t] * inv);
}
__global__ void k_nodal2(const float* __restrict__ a2s, const float* __restrict__ a2d) {
    int n = blockIdx.x * blockDim.x + threadIdx.x;
    if (n >= NN) return;
    float s = 0.f, d = 0.f;
    for (int c = 0; c < CC; c++) {
        float gv = g_g2[n * CC + c];
        s += gv * a2s[c];
        d += gv * a2d[c];
    }
    g_alS2[n] = s;
    g_alD2[n] = d;
    int dg = g_count[n];
    float inv = 1.f / (float)(dg > 0 ? dg : 1);
    g_es2[n] = lrelu1(s + d + g_aes2[n] * inv);
}

// ---------------- layer-1 aggregation: fused exp + softmax + gather ----------------
// Warp per node. Lane = (h<<3)|q: h = head (channels lane*4), q = edge-in-chunk.
__global__ void k_agg1(const float* __restrict__ b1) {
    int n = (blockIdx.x * blockDim.x + threadIdx.x) >> 5;
    int lane = threadIdx.x & 31;
    if (n >= NN) return;
    int rs = g_rowptr[n], re = g_rowptr[n + 1];
    int h = lane >> 3, q = lane & 7;
    float aDh = g_alD1[n * 4 + h];
    float pSelf = __expf(g_es1[n * 4 + h]);
    float4 hv = *(const float4*)&g_h1[n * HC + lane * 4];
    float4 acc = make_float4(pSelf * hv.x, pSelf * hv.y, pSelf * hv.z, pSelf * hv.w);
    float zpart = 0.f;
    for (int j0 = rs; j0 < re; j0 += 8) {
        int m = re - j0; if (m > 8) m = 8;
        int s_q = 0; float p_q = 0.f;
        if (q < m) {
            s_q = g_cs[j0 + q];
            float ae = g_alE1c[(j0 + q) * 4 + h];
            p_q = __expf(lrelu1(g_alS1[s_q * 4 + h] + aDh + ae));
        }
        zpart += p_q;
        for (int qq = 0; qq < m; qq++) {
            int srcLane = (h << 3) | qq;
            float p = __shfl_sync(0xffffffffu, p_q, srcLane);
            int s   = __shfl_sync(0xffffffffu, s_q, srcLane);
            float4 sv = *(const float4*)&g_h1[s * HC + lane * 4];
            acc.x += p * sv.x; acc.y += p * sv.y;
            acc.z += p * sv.z; acc.w += p * sv.w;
        }
    }
    // reduce z over q within the 8-lane head group
    #pragma unroll
    for (int o = 4; o; o >>= 1) zpart += __shfl_xor_sync(0xffffffffu, zpart, o);
    float iz = 1.f / (zpart + pSelf);
    int j4 = lane * 4;
    g_x1[n * HC + j4 + 0] = elu1(acc.x * iz + b1[j4 + 0]);
    g_x1[n * HC + j4 + 1] = elu1(acc.y * iz + b1[j4 + 1]);
    g_x1[n * HC + j4 + 2] = elu1(acc.z * iz + b1[j4 + 2]);
    g_x1[n * HC + j4 + 3] = elu1(acc.w * iz + b1[j4 + 3]);
}

// ---------------- layer-2 exp(logit) per CSR slot ----------------
__global__ void k_p2() {
    int j = blockIdx.x * blockDim.x + threadIdx.x;
    if (j >= EE) return;
    int s = g_cs[j], d = g_cd[j];
    g_p2c[j] = __expf(lrelu1(g_alS2[s] + g_alD2[d] + g_alE2c[j]));
}

// ---------------- layer-2 aggregation + alpha output ----------------
__global__ void k_agg2(const float* __restrict__ b2, float* __restrict__ h2out,
                       float* __restrict__ alphaOut) {
    int n = (blockIdx.x * blockDim.x + threadIdx.x) >> 5;
    int lane = threadIdx.x & 31;
    if (n >= NN) return;
    int rs = g_rowptr[n], re = g_rowptr[n + 1];
    float pSelf = __expf(g_es2[n]);
    float acc = pSelf * g_g2[n * CC + lane];
    float zsum = pSelf;
    for (int j = rs; j < re; j++) {
        int s = g_cs[j];
        float p = g_p2c[j];
        acc += p * g_g2[s * CC + lane];
        zsum += p;
    }
    float iz = 1.f / zsum;
    h2out[n * CC + lane] = elu1(acc * iz + b2[lane]);
    if (alphaOut != nullptr) {
        for (int j = rs + lane; j < re; j += 32)
            alphaOut[g_ce[j]] = g_p2c[j] * iz;
        if (lane == 0) alphaOut[EE + n] = pSelf * iz;
    }
}

// ---------------- edge_index output (as float) ----------------
__global__ void k_write_ei(const int* __restrict__ ei, float* __restrict__ out) {
    int t = blockIdx.x * blockDim.x + threadIdx.x;
    if (t >= EP) return;
    float sv = (t < EE) ? (float)ei[t]      : (float)(t - EE);
    float dv = (t < EE) ? (float)ei[EE + t] : (float)(t - EE);
    out[t] = sv;
    out[EP + t] = dv;
}

// ---------------- launch ----------------
extern "C" void kernel_launch(void* const* d_in, const int* in_sizes, int n_in,
                              void* d_out, int out_size) {
    const float* x    = (const float*)d_in[0];
    const int*   ei   = (const int*)d_in[1];
    const float* eattr= (const float*)d_in[2];
    const float* W1   = (const float*)d_in[3];
    const float* W1e  = (const float*)d_in[4];
    const float* a1s  = (const float*)d_in[5];
    const float* a1d  = (const float*)d_in[6];
    const float* a1e  = (const float*)d_in[7];
    const float* b1   = (const float*)d_in[8];
    const float* W2   = (const float*)d_in[9];
    const float* W2e  = (const float*)d_in[10];
    const float* a2s  = (const float*)d_in[11];
    const float* a2d  = (const float*)d_in[12];
    const float* a2e  = (const float*)d_in[13];
    const float* b2   = (const float*)d_in[14];
    float* out = (float*)d_out;

    bool hasEI = out_size >= NN * CC + 2 * EP;
    bool hasAl = out_size >= NN * CC + 2 * EP + EP;
    float* h2out  = out;
    float* eiout  = hasEI ? out + NN * CC : nullptr;
    float* alphaO = hasAl ? out + NN * CC + 2 * EP : nullptr;

    k_zero   <<<1024, 256>>>();
    k_prep   <<<1, 64>>>(W1e, a1e, W2e, a2e);

    // CSR build (real edges only); g_count survives as in-degree
    k_csr_count  <<<(EE + 255) / 256, 256>>>(ei);
    k_scan_part  <<<SCAN_G, SCAN_B>>>();
    k_scan_top   <<<1, 128>>>();
    k_scan_down  <<<SCAN_G, SCAN_B>>>();
    k_cursor     <<<(NN + 255) / 256, 256>>>();
    k_csr_scatter<<<(EE + 255) / 256, 256>>>(ei);

    k_edge_al<<<(EE + 255) / 256, 256>>>(eattr, ei);

    // layer 1
    k_mm1    <<<((NN / 4) * 32 + 255) / 256, 256>>>(x, W1);
    k_nodal1 <<<(NN * HH + 255) / 256, 256>>>(a1s, a1d);
    k_agg1   <<<(NN * 32 + 255) / 256, 256>>>(b1);

    // layer 2
    k_mm2    <<<((NN / 4) * 8 + 255) / 256, 256>>>(W2);
    k_nodal2 <<<(NN + 255) / 256, 256>>>(a2s, a2d);
    k_p2     <<<(EE + 255) / 256, 256>>>();
    k_agg2   <<<(NN * 32 + 255) / 256, 256>>>(b2, h2out, alphaO);

    if (eiout) k_write_ei<<<(EP + 255) / 256, 256>>>(ei, eiout);
}